// round 5
// baseline (speedup 1.0000x reference)
#include <cuda_runtime.h>

#define TSEQ    1024
#define NB      512
#define RMAX    7
#define NDIRBLK 74
#define NBLK    (2 * NDIRBLK)
#define VOCABP1 50001
#define LOG2E   1.4426950408889634f

// Precomputed zx table: zw[dir][token][gate] = emb[token] @ W_dir + b_dir
__device__ float g_zw[2][VOCABP1][256];
// final hidden states: [dir][batch][64]
__device__ float g_h[2 * NB * 64];

static __device__ __forceinline__ unsigned long long pk2(float lo, float hi) {
    unsigned long long r;
    asm("mov.b64 %0, {%1,%2};" : "=l"(r) : "f"(lo), "f"(hi));
    return r;
}
static __device__ __forceinline__ void upk2(unsigned long long v, float &lo, float &hi) {
    asm("mov.b64 {%0,%1}, %2;" : "=f"(lo), "=f"(hi) : "l"(v));
}
static __device__ __forceinline__ void ffma2(unsigned long long &d,
                                             unsigned long long a,
                                             unsigned long long b) {
    asm("fma.rn.f32x2 %0, %1, %2, %0;" : "+l"(d) : "l"(a), "l"(b));
}
static __device__ __forceinline__ float ex2a(float x) {
    float r; asm("ex2.approx.f32 %0, %1;" : "=f"(r) : "f"(x)); return r;
}
static __device__ __forceinline__ float rcpa(float x) {
    float r; asm("rcp.approx.f32 %0, %1;" : "=f"(r) : "f"(x)); return r;
}

// ============================================================================
// Phase 1: zw[dir][v][j] = sum_k emb[v][k] * W_dir[k][j] + b_dir[j]
// ============================================================================
extern "C" __global__ void __launch_bounds__(256, 2)
zw_kernel(const float* __restrict__ emb,
          const float* __restrict__ Wf, const float* __restrict__ bf,
          const float* __restrict__ Wb, const float* __restrict__ bb)
{
    __shared__ __align__(16) float ebuf[64][64];
    const int dir  = blockIdx.y;
    const int base = blockIdx.x * 64;
    const int j    = threadIdx.x;
    const float* W  = dir ? Wb : Wf;
    const float* bv = dir ? bb : bf;

    unsigned long long wreg[32];
#pragma unroll
    for (int p = 0; p < 32; p++)
        wreg[p] = pk2(W[(2 * p) * 256 + j], W[(2 * p + 1) * 256 + j]);
    const float bj = bv[j];

#pragma unroll
    for (int i = 0; i < 16; i++) {
        const int lin = i * 256 + j;
        const int r = lin >> 6, c = lin & 63;
        const int row = base + r;
        ebuf[r][c] = (row < VOCABP1) ? emb[(long long)row * 64 + c] : 0.f;
    }
    __syncthreads();

    float* outp = &g_zw[dir][0][0];
#pragma unroll 1
    for (int r = 0; r < 64; r++) {
        if (base + r >= VOCABP1) break;
        const ulonglong2* srow = (const ulonglong2*)(&ebuf[r][0]);
        unsigned long long a0 = 0ull, a1 = 0ull;
#pragma unroll
        for (int q = 0; q < 8; q++) {
            const ulonglong2 v0 = srow[2 * q];
            const ulonglong2 v1 = srow[2 * q + 1];
            ffma2(a0, v0.x, wreg[4 * q + 0]);
            ffma2(a1, v0.y, wreg[4 * q + 1]);
            ffma2(a0, v1.x, wreg[4 * q + 2]);
            ffma2(a1, v1.y, wreg[4 * q + 3]);
        }
        float p0, p1, q0, q1;
        upk2(a0, p0, p1);
        upk2(a1, q0, q1);
        outp[(long long)(base + r) * 256 + j] = bj + ((p0 + q0) + (p1 + q1));
    }
}

// ============================================================================
// Phase 2: recurrent h@U + gates, fully fused, ONE barrier per step.
// 148 blocks x 512 threads. Warp layout: lane = (gate g = lane>>3, s = lane&7);
// warp wid covers unit-group ug = wid&7, rows {0..3} (wid<8) or {4..6} (wid>=8).
// Each lane computes z(gate,unit) in registers; gate-gather via 4 shfl.idx;
// sigm/tanh unified as ex2+rcp with per-lane constants (2 MUFU for 4 gates).
// hs double-buffered, token ids triple-buffered, zx prefetched to registers.
// ============================================================================
extern "C" __global__ void __launch_bounds__(512, 1)
lstm_kernel(const void* __restrict__ xraw,
            const float* __restrict__ Uf, const float* __restrict__ Ub)
{
    __shared__ __align__(16) float hs[2][RMAX][64];   // double-buffered hidden state
    __shared__ int idxs[3][8];                        // token ids, 3-slot ring

    const int tid  = threadIdx.x;
    const int wid  = tid >> 5;
    const int lane = tid & 31;
    const int g    = lane >> 3;      // gate 0..3
    const int s    = lane & 7;       // unit within group

    const int dir   = (blockIdx.x >= NDIRBLK) ? 1 : 0;
    const int bslot = blockIdx.x - dir * NDIRBLK;
    const int base  = bslot * RMAX;
    const int nrows = min(RMAX, NB - base);

    const int ug   = wid & 7;        // unit group 0..7
    const int hi   = wid >> 3;       // row half
    const int rbeg = hi * 4;
    const int rend = hi ? min(nrows, 7) : min(nrows, 4);
    const int nr   = rend - rbeg;    // warp-uniform

    const int col = g * 64 + ug * 8 + s;

    const int*       x32 = (const int*)xraw;
    const long long* x64 = (const long long*)xraw;
    const bool is64 = ((x32[1] | x32[3] | x32[5] | x32[7]) == 0);

    const float* U   = dir ? Ub : Uf;
    const float* zwd = &g_zw[dir][0][0];

    unsigned long long wreg[32];
#pragma unroll
    for (int p = 0; p < 32; p++)
        wreg[p] = pk2(U[(2 * p) * 256 + col], U[(2 * p + 1) * 256 + col]);

    // unified activation constants: gate 2 (candidate) uses tanh, others sigmoid
    const float Sg = (g == 2) ? (2.f * LOG2E) : (-LOG2E);
    const float Ag = (g == 2) ? 1.f : 0.f;
    const float Bg = (g == 2) ? -2.f : 1.f;

    // ---- prologue: token ids for steps 0..2; zero hs buf 0 ----
    if (tid < nrows) {
        const long long xb = (long long)(base + tid) * TSEQ;
#pragma unroll
        for (int q = 0; q < 3; q++) {
            const int tq = dir ? (TSEQ - 1 - q) : q;
            idxs[q][tid] = is64 ? (int)x64[xb + tq] : x32[xb + tq];
        }
    }
    if ((tid >> 6) < RMAX) hs[0][tid >> 6][tid & 63] = 0.f;
    __syncthreads();

    float zcur[4], creg[4], hreg[4];
#pragma unroll
    for (int i = 0; i < 4; i++) { creg[i] = 0.f; hreg[i] = 0.f; zcur[i] = 0.f; }
#pragma unroll
    for (int i = 0; i < 4; i++) {
        if (i < nr) {
            const int tok = idxs[0][rbeg + i];
            zcur[i] = zwd[(long long)tok * 256 + col];
        }
    }

#pragma unroll 1
    for (int t = 0; t < TSEQ; t++) {
        const int p = t & 1;

        // masks for this step (slot t%3, written >= 2 barriers ago)
        int mk[4];
#pragma unroll
        for (int i = 0; i < 4; i++)
            mk[i] = (i < nr) ? idxs[t % 3][rbeg + i] : 0;

        // prefetch zx for step t+1 into registers
        float znext[4] = {0.f, 0.f, 0.f, 0.f};
        const bool have_e = (t + 1 < TSEQ);
        if (have_e) {
#pragma unroll
            for (int i = 0; i < 4; i++) {
                if (i < nr) {
                    const int tok = idxs[(t + 1) % 3][rbeg + i];
                    znext[i] = zwd[(long long)tok * 256 + col];
                }
            }
        }
        // prefetch token id for step t+2 into ring slot (t+2)%3
        if ((tid < nrows) && (t + 2 < TSEQ)) {
            const int tn = dir ? (TSEQ - 1 - (t + 2)) : (t + 2);
            const long long xb = (long long)(base + tid) * TSEQ;
            idxs[(t + 2) % 3][tid] = is64 ? (int)x64[xb + tn] : x32[xb + tn];
        }

        // ===== fused stage B + C, per row =====
#pragma unroll
        for (int i = 0; i < 4; i++) {
            if (i >= nr) break;
            const int r = rbeg + i;
            const ulonglong2* hp = (const ulonglong2*)(&hs[p][r][0]);
            unsigned long long a0 = 0ull, a1 = 0ull;
#pragma unroll
            for (int q = 0; q < 8; q++) {
                const ulonglong2 v0 = hp[2 * q];
                const ulonglong2 v1 = hp[2 * q + 1];
                ffma2(a0, v0.x, wreg[4 * q + 0]);
                ffma2(a1, v0.y, wreg[4 * q + 1]);
                ffma2(a0, v1.x, wreg[4 * q + 2]);
                ffma2(a1, v1.y, wreg[4 * q + 3]);
            }
            float p0, p1, q0, q1;
            upk2(a0, p0, p1);
            upk2(a1, q0, q1);
            const float z = zcur[i] + ((p0 + q0) + (p1 + q1));

            // unified activation: sigm / tanh in 2 MUFU for all 4 gates
            const float e   = ex2a(z * Sg);
            const float rc  = rcpa(e + 1.f);
            const float act = fmaf(Bg, rc, Ag);

            // gather the 4 gate activations for my unit s
            const float iv = __shfl_sync(0xffffffffu, act, s);
            const float fv = __shfl_sync(0xffffffffu, act, 8 + s);
            const float gv = __shfl_sync(0xffffffffu, act, 16 + s);
            const float ov = __shfl_sync(0xffffffffu, act, 24 + s);

            const float cn  = fmaf(fv, creg[i], iv * gv);
            const float e2  = ex2a(cn * (2.f * LOG2E));
            const float r2  = rcpa(e2 + 1.f);
            const float tcn = fmaf(-2.f, r2, 1.f);
            const float hn  = ov * tcn;

            if (mk[i] != 0) { creg[i] = cn; hreg[i] = hn; }
            if (g == 0) hs[p ^ 1][r][ug * 8 + s] = hreg[i];
        }

#pragma unroll
        for (int i = 0; i < 4; i++) zcur[i] = znext[i];
        __syncthreads();
    }

    if (g == 0) {
#pragma unroll
        for (int i = 0; i < 4; i++) {
            if (i >= nr) break;
            const int r = rbeg + i;
            g_h[(dir * NB + (base + r)) * 64 + ug * 8 + s] = hreg[i];
        }
    }
}

// ============================================================================
// Head: out[b] = relu(concat(hf,hb) @ W1 + b1) @ W2 + b2
// ============================================================================
extern "C" __global__ void head_kernel(const float* __restrict__ W1,
                                       const float* __restrict__ b1,
                                       const float* __restrict__ W2,
                                       const float* __restrict__ b2,
                                       float* __restrict__ out)
{
    const int b = blockIdx.x;
    const int u = threadIdx.x;
    const float* hf = &g_h[b * 64];
    const float* hb = &g_h[(NB + b) * 64];
    float acc = b1[u];
#pragma unroll
    for (int k = 0; k < 64; k++) acc = fmaf(hf[k], W1[k * 32 + u], acc);
#pragma unroll
    for (int k = 0; k < 64; k++) acc = fmaf(hb[k], W1[(64 + k) * 32 + u], acc);
    float v = fmaxf(acc, 0.f) * W2[u];
#pragma unroll
    for (int off = 16; off > 0; off >>= 1)
        v += __shfl_xor_sync(0xffffffffu, v, off);
    if (u == 0) out[b] = v + b2[0];
}

extern "C" void kernel_launch(void* const* d_in, const int* in_sizes, int n_in,
                              void* d_out, int out_size)
{
    const void*  x   = d_in[0];
    const float* emb = (const float*)d_in[1];
    const float* Wf  = (const float*)d_in[2];
    const float* Uf  = (const float*)d_in[3];
    const float* bf  = (const float*)d_in[4];
    const float* Wb  = (const float*)d_in[5];
    const float* Ub  = (const float*)d_in[6];
    const float* bb  = (const float*)d_in[7];
    const float* W1  = (const float*)d_in[8];
    const float* b1  = (const float*)d_in[9];
    const float* W2  = (const float*)d_in[10];
    const float* b2  = (const float*)d_in[11];

    zw_kernel<<<dim3((VOCABP1 + 63) / 64, 2), 256>>>(emb, Wf, bf, Wb, bb);
    lstm_kernel<<<NBLK, 512>>>(x, Uf, Ub);
    head_kernel<<<NB, 32>>>(W1, b1, W2, b2, (float*)d_out);
}

// round 6
// speedup vs baseline: 1.2950x; 1.2950x over previous
#include <cuda_runtime.h>

#define TSEQ    1024
#define NB      512
#define RMAX    7
#define NDIRBLK 74
#define NBLK    (2 * NDIRBLK)
#define VOCABP1 50001
#define LOG2E   1.4426950408889634f

// Precomputed zx table: zw[dir][token][gate] = emb[token] @ W_dir + b_dir
__device__ float g_zw[2][VOCABP1][256];
// final hidden states: [dir][batch][64]
__device__ float g_h[2 * NB * 64];

static __device__ __forceinline__ unsigned long long pk2(float lo, float hi) {
    unsigned long long r;
    asm("mov.b64 %0, {%1,%2};" : "=l"(r) : "f"(lo), "f"(hi));
    return r;
}
static __device__ __forceinline__ void upk2(unsigned long long v, float &lo, float &hi) {
    asm("mov.b64 {%0,%1}, %2;" : "=f"(lo), "=f"(hi) : "l"(v));
}
static __device__ __forceinline__ void ffma2(unsigned long long &d,
                                             unsigned long long a,
                                             unsigned long long b) {
    asm("fma.rn.f32x2 %0, %1, %2, %0;" : "+l"(d) : "l"(a), "l"(b));
}
static __device__ __forceinline__ float ex2a(float x) {
    float r; asm("ex2.approx.f32 %0, %1;" : "=f"(r) : "f"(x)); return r;
}
static __device__ __forceinline__ float rcpa(float x) {
    float r; asm("rcp.approx.f32 %0, %1;" : "=f"(r) : "f"(x)); return r;
}
static __device__ __forceinline__ float sigm_fast(float x) {
    // 1/(1+exp(-x)) via ex2+rcp approx
    return rcpa(1.f + ex2a(-LOG2E * x));
}
static __device__ __forceinline__ float tanh_fast(float x) {
    // 1 - 2/(exp(2x)+1)
    return fmaf(-2.f, rcpa(1.f + ex2a((2.f * LOG2E) * x)), 1.f);
}

// ============================================================================
// Phase 1: zw[dir][v][j] = sum_k emb[v][k] * W_dir[k][j] + b_dir[j]
// ============================================================================
extern "C" __global__ void __launch_bounds__(256, 2)
zw_kernel(const float* __restrict__ emb,
          const float* __restrict__ Wf, const float* __restrict__ bf,
          const float* __restrict__ Wb, const float* __restrict__ bb)
{
    __shared__ __align__(16) float ebuf[64][64];
    const int dir  = blockIdx.y;
    const int base = blockIdx.x * 64;
    const int j    = threadIdx.x;
    const float* W  = dir ? Wb : Wf;
    const float* bv = dir ? bb : bf;

    unsigned long long wreg[32];
#pragma unroll
    for (int p = 0; p < 32; p++)
        wreg[p] = pk2(W[(2 * p) * 256 + j], W[(2 * p + 1) * 256 + j]);
    const float bj = bv[j];

#pragma unroll
    for (int i = 0; i < 16; i++) {
        const int lin = i * 256 + j;
        const int r = lin >> 6, c = lin & 63;
        const int row = base + r;
        ebuf[r][c] = (row < VOCABP1) ? emb[(long long)row * 64 + c] : 0.f;
    }
    __syncthreads();

    float* outp = &g_zw[dir][0][0];
#pragma unroll 1
    for (int r = 0; r < 64; r++) {
        if (base + r >= VOCABP1) break;
        const ulonglong2* srow = (const ulonglong2*)(&ebuf[r][0]);
        unsigned long long a0 = 0ull, a1 = 0ull;
#pragma unroll
        for (int q = 0; q < 8; q++) {
            const ulonglong2 v0 = srow[2 * q];
            const ulonglong2 v1 = srow[2 * q + 1];
            ffma2(a0, v0.x, wreg[4 * q + 0]);
            ffma2(a1, v0.y, wreg[4 * q + 1]);
            ffma2(a0, v1.x, wreg[4 * q + 2]);
            ffma2(a1, v1.y, wreg[4 * q + 3]);
        }
        float p0, p1, q0, q1;
        upk2(a0, p0, p1);
        upk2(a1, q0, q1);
        outp[(long long)(base + r) * 256 + j] = bj + ((p0 + q0) + (p1 + q1));
    }
}

// ============================================================================
// Phase 2: recurrent h@U + gates (R3 two-stage skeleton).
// 148 blocks x 512 threads. Stage B: col = tid&255, row-halves 4/3.
// Stage C: fast approx activations (ex2+rcp), one task per thread.
// ============================================================================
extern "C" __global__ void __launch_bounds__(512, 1)
lstm_kernel(const void* __restrict__ xraw,
            const float* __restrict__ Uf, const float* __restrict__ Ub)
{
    __shared__ __align__(16) float hs[RMAX][64];          // hidden state
    __shared__ __align__(16) float zs[RMAX][256];         // gate pre-activations
    __shared__ __align__(16) float zxs[2][RMAX][256];     // zx double buffer
    __shared__ int   idxs[2][8];                          // token ids, ping-pong

    const int tid = threadIdx.x;
    const int dir   = (blockIdx.x >= NDIRBLK) ? 1 : 0;
    const int bslot = blockIdx.x - dir * NDIRBLK;
    const int base  = bslot * RMAX;
    const int nrows = min(RMAX, NB - base);

    const int*       x32 = (const int*)xraw;
    const long long* x64 = (const long long*)xraw;
    const bool is64 = ((x32[1] | x32[3] | x32[5] | x32[7]) == 0);

    const float* U   = dir ? Ub : Uf;
    const float* zwd = &g_zw[dir][0][0];

    const int col   = tid & 255;
    const int rhalf = tid >> 8;
    const int r0    = rhalf ? 4 : 0;
    const int rcnt  = rhalf ? 3 : 4;

    unsigned long long wreg[32];
#pragma unroll
    for (int p = 0; p < 32; p++)
        wreg[p] = pk2(U[(2 * p) * 256 + col], U[(2 * p + 1) * 256 + col]);

    const int cu = tid & 63;        // stage C: hidden unit
    const int cr = tid >> 6;        // stage C: task (0..7)
    const int pr = tid >> 6;        // zx prefetch: task row
    const int pq = tid & 63;        // zx prefetch: float4 group

    // ---- prologue ----
    if (tid < nrows) {
        const long long xb = (long long)(base + tid) * TSEQ;
        const int t0 = dir ? (TSEQ - 1) : 0;
        const int t1 = dir ? (TSEQ - 2) : 1;
        idxs[0][tid] = is64 ? (int)x64[xb + t0] : x32[xb + t0];
        idxs[1][tid] = is64 ? (int)x64[xb + t1] : x32[xb + t1];
    }
    if (cr < RMAX) hs[cr][cu] = 0.f;
    __syncthreads();
    if (pr < nrows) {   // zx for step 0
        const int tok = idxs[0][pr];
        const float4 v = *(const float4*)(zwd + (long long)tok * 256 + 4 * pq);
        *(float4*)&zxs[0][pr][4 * pq] = v;
    }
    float hreg = 0.f, creg = 0.f;
    __syncthreads();

    for (int t = 0; t < TSEQ; t++) {
        const int pcur = t & 1, pnxt = pcur ^ 1;

        const int m = (cr < nrows) ? idxs[pcur][cr] : 0;   // mask token

        // prefetch zx row for step t+1
        float4 zv = make_float4(0.f, 0.f, 0.f, 0.f);
        const int have_e = (t + 1 < TSEQ) && (pr < nrows);
        if (have_e) {
            const int tok = idxs[pnxt][pr];
            zv = *(const float4*)(zwd + (long long)tok * 256 + 4 * pq);
        }
        // prefetch token id for step t+2
        long long nidx = 0;
        const int have_i = (tid < nrows) && (t + 2 < TSEQ);
        if (have_i) {
            const int tn = dir ? (TSEQ - 1 - (t + 2)) : (t + 2);
            const long long xb = (long long)(base + tid) * TSEQ;
            nidx = is64 ? x64[xb + tn] : (long long)x32[xb + tn];
        }

        // ========== stage B: z = zx + h @ U ==========
#pragma unroll
        for (int i = 0; i < 4; i++) {
            if (i >= rcnt) break;
            const int r = r0 + i;
            if (r >= nrows) break;
            const ulonglong2* hp = (const ulonglong2*)(&hs[r][0]);
            // fold zx into the accumulator init: final sum = p0+p1+q0+q1
            unsigned long long a0 = pk2(zxs[pcur][r][col], 0.f);
            unsigned long long a1 = 0ull;
#pragma unroll
            for (int q = 0; q < 8; q++) {
                const ulonglong2 v0 = hp[2 * q];
                const ulonglong2 v1 = hp[2 * q + 1];
                ffma2(a0, v0.x, wreg[4 * q + 0]);
                ffma2(a1, v0.y, wreg[4 * q + 1]);
                ffma2(a0, v1.x, wreg[4 * q + 2]);
                ffma2(a1, v1.y, wreg[4 * q + 3]);
            }
            float p0, p1, q0, q1;
            upk2(a0, p0, p1);
            upk2(a1, q0, q1);
            zs[r][col] = (p0 + q0) + (p1 + q1);
        }
        // commit zx prefetch into the other buffer (read at t+1 after bar)
        if (have_e) *(float4*)&zxs[pnxt][pr][4 * pq] = zv;
        __syncthreads();

        // ========== stage C: gates + state update (approx activations) ======
        if (cr < nrows) {
            const float zi = zs[cr][cu];
            const float zf = zs[cr][64 + cu];
            const float zg = zs[cr][128 + cu];
            const float zo = zs[cr][192 + cu];
            const float ig = sigm_fast(zi);
            const float fg = sigm_fast(zf);
            const float gg = tanh_fast(zg);
            const float og = sigm_fast(zo);
            const float cn = fmaf(fg, creg, ig * gg);
            const float hn = og * tanh_fast(cn);
            if (m != 0) { creg = cn; hreg = hn; }
            hs[cr][cu] = hreg;
        }
        if (have_i) idxs[pcur][tid] = (int)nidx;   // becomes idx[t+2]
        __syncthreads();
    }

    if (cr < nrows)
        g_h[(dir * NB + (base + cr)) * 64 + cu] = hreg;
}

// ============================================================================
// Head: out[b] = relu(concat(hf,hb) @ W1 + b1) @ W2 + b2
// ============================================================================
extern "C" __global__ void head_kernel(const float* __restrict__ W1,
                                       const float* __restrict__ b1,
                                       const float* __restrict__ W2,
                                       const float* __restrict__ b2,
                                       float* __restrict__ out)
{
    const int b = blockIdx.x;
    const int u = threadIdx.x;
    const float* hf = &g_h[b * 64];
    const float* hb = &g_h[(NB + b) * 64];
    float acc = b1[u];
#pragma unroll
    for (int k = 0; k < 64; k++) acc = fmaf(hf[k], W1[k * 32 + u], acc);
#pragma unroll
    for (int k = 0; k < 64; k++) acc = fmaf(hb[k], W1[(64 + k) * 32 + u], acc);
    float v = fmaxf(acc, 0.f) * W2[u];
#pragma unroll
    for (int off = 16; off > 0; off >>= 1)
        v += __shfl_xor_sync(0xffffffffu, v, off);
    if (u == 0) out[b] = v + b2[0];
}

extern "C" void kernel_launch(void* const* d_in, const int* in_sizes, int n_in,
                              void* d_out, int out_size)
{
    const void*  x   = d_in[0];
    const float* emb = (const float*)d_in[1];
    const float* Wf  = (const float*)d_in[2];
    const float* Uf  = (const float*)d_in[3];
    const float* bf  = (const float*)d_in[4];
    const float* Wb  = (const float*)d_in[5];
    const float* Ub  = (const float*)d_in[6];
    const float* bb  = (const float*)d_in[7];
    const float* W1  = (const float*)d_in[8];
    const float* b1  = (const float*)d_in[9];
    const float* W2  = (const float*)d_in[10];
    const float* b2  = (const float*)d_in[11];

    zw_kernel<<<dim3((VOCABP1 + 63) / 64, 2), 256>>>(emb, Wf, bf, Wb, bb);
    lstm_kernel<<<NBLK, 512>>>(x, Uf, Ub);
    head_kernel<<<NB, 32>>>(W1, b1, W2, b2, (float*)d_out);
}

// round 8
// speedup vs baseline: 1.6731x; 1.2920x over previous
#include <cuda_runtime.h>
#include <cuda_fp16.h>

#define TSEQ    1024
#define NB      512
#define RMAX    7
#define NDIRBLK 74
#define NBLK    (2 * NDIRBLK)
#define VOCABP1 50001
#define LOG2E   1.4426950408889634f
#define ZSTR    264   // zs row stride (floats), padded vs 256 for bank spread
#define HSTR    72    // hs16 row stride (halves), padded vs 64

// Precomputed zx table: zw[dir][token][gate] = emb[token] @ W_dir + b_dir
__device__ float g_zw[2][VOCABP1][256];
// final hidden states: [dir][batch][64]
__device__ float g_h[2 * NB * 64];

static __device__ __forceinline__ unsigned long long pk2(float lo, float hi) {
    unsigned long long r;
    asm("mov.b64 %0, {%1,%2};" : "=l"(r) : "f"(lo), "f"(hi));
    return r;
}
static __device__ __forceinline__ void upk2(unsigned long long v, float &lo, float &hi) {
    asm("mov.b64 {%0,%1}, %2;" : "=f"(lo), "=f"(hi) : "l"(v));
}
static __device__ __forceinline__ void ffma2(unsigned long long &d,
                                             unsigned long long a,
                                             unsigned long long b) {
    asm("fma.rn.f32x2 %0, %1, %2, %0;" : "+l"(d) : "l"(a), "l"(b));
}
static __device__ __forceinline__ float ex2a(float x) {
    float r; asm("ex2.approx.f32 %0, %1;" : "=f"(r) : "f"(x)); return r;
}
static __device__ __forceinline__ float rcpa(float x) {
    float r; asm("rcp.approx.f32 %0, %1;" : "=f"(r) : "f"(x)); return r;
}
static __device__ __forceinline__ float sigm_fast(float x) {
    return rcpa(1.f + ex2a(-LOG2E * x));
}
static __device__ __forceinline__ float tanh_fast(float x) {
    return fmaf(-2.f, rcpa(1.f + ex2a((2.f * LOG2E) * x)), 1.f);
}
static __device__ __forceinline__ void hmma16816(float* d,
                                                 unsigned a0, unsigned a1,
                                                 unsigned a2, unsigned a3,
                                                 unsigned b0, unsigned b1) {
    asm volatile(
        "mma.sync.aligned.m16n8k16.row.col.f32.f16.f16.f32 "
        "{%0,%1,%2,%3}, {%4,%5,%6,%7}, {%8,%9}, {%0,%1,%2,%3};\n"
        : "+f"(d[0]), "+f"(d[1]), "+f"(d[2]), "+f"(d[3])
        : "r"(a0), "r"(a1), "r"(a2), "r"(a3), "r"(b0), "r"(b1));
}

// ============================================================================
// Phase 1: zw[dir][v][j] = sum_k emb[v][k] * W_dir[k][j] + b_dir[j]
// ============================================================================
extern "C" __global__ void __launch_bounds__(256, 2)
zw_kernel(const float* __restrict__ emb,
          const float* __restrict__ Wf, const float* __restrict__ bf,
          const float* __restrict__ Wb, const float* __restrict__ bb)
{
    __shared__ __align__(16) float ebuf[64][64];
    const int dir  = blockIdx.y;
    const int base = blockIdx.x * 64;
    const int j    = threadIdx.x;
    const float* W  = dir ? Wb : Wf;
    const float* bv = dir ? bb : bf;

    unsigned long long wreg[32];
#pragma unroll
    for (int p = 0; p < 32; p++)
        wreg[p] = pk2(W[(2 * p) * 256 + j], W[(2 * p + 1) * 256 + j]);
    const float bj = bv[j];

#pragma unroll
    for (int i = 0; i < 16; i++) {
        const int lin = i * 256 + j;
        const int r = lin >> 6, c = lin & 63;
        const int row = base + r;
        ebuf[r][c] = (row < VOCABP1) ? emb[(long long)row * 64 + c] : 0.f;
    }
    __syncthreads();

    float* outp = &g_zw[dir][0][0];
#pragma unroll 1
    for (int r = 0; r < 64; r++) {
        if (base + r >= VOCABP1) break;
        const ulonglong2* srow = (const ulonglong2*)(&ebuf[r][0]);
        unsigned long long a0 = 0ull, a1 = 0ull;
#pragma unroll
        for (int q = 0; q < 8; q++) {
            const ulonglong2 v0 = srow[2 * q];
            const ulonglong2 v1 = srow[2 * q + 1];
            ffma2(a0, v0.x, wreg[4 * q + 0]);
            ffma2(a1, v0.y, wreg[4 * q + 1]);
            ffma2(a0, v1.x, wreg[4 * q + 2]);
            ffma2(a1, v1.y, wreg[4 * q + 3]);
        }
        float p0, p1, q0, q1;
        upk2(a0, p0, p1);
        upk2(a1, q0, q1);
        outp[(long long)(base + r) * 256 + j] = bj + ((p0 + q0) + (p1 + q1));
    }
}

// ============================================================================
// Phase 2: recurrent h@U via tensor cores (mma.sync m16n8k16 fp16->fp32).
// 148 blocks x 512 threads (16 warps). Warp w owns cols [16w, 16w+16).
// U fp16 B-fragments permanently in registers (16/lane). h kept fp16 in smem
// (double-buffered, stride-72 padded -> conflict-free LDS.32 A-fragments).
// zx loads initialize the MMA accumulators. Rows 8..15 of the M=16 tile are
// structurally zero (nrows<=7): a1/a3 (rows 8-15 slots) are constant zero;
// the k 8-15 half of each 16-chunk goes in the a2 slot (PTX fragment layout).
// Stage C (gates): one (row,unit) per thread, fast ex2/rcp activations.
// ============================================================================
extern "C" __global__ void __launch_bounds__(512, 1)
lstm_kernel(const void* __restrict__ xraw,
            const float* __restrict__ Uf, const float* __restrict__ Ub)
{
    __shared__ __align__(16) __half hs16[2][8][HSTR];  // fp16 hidden, double buf
    __shared__ __align__(16) float  zs[8][ZSTR];       // gate pre-activations
    __shared__ int idxs[3][8];                         // token ids, 3-slot ring

    const int tid  = threadIdx.x;
    const int wid  = tid >> 5;
    const int lane = tid & 31;
    const int lq   = lane >> 2;        // 0..7 : MMA row group
    const int lr   = lane & 3;         // 0..3 : k pair base

    const int dir   = (blockIdx.x >= NDIRBLK) ? 1 : 0;
    const int bslot = blockIdx.x - dir * NDIRBLK;
    const int base  = bslot * RMAX;
    const int nrows = min(RMAX, NB - base);

    const int n0 = wid * 16;           // this warp's column slice

    const int*       x32 = (const int*)xraw;
    const long long* x64 = (const long long*)xraw;
    const bool is64 = ((x32[1] | x32[3] | x32[5] | x32[7]) == 0);

    const float* U   = dir ? Ub : Uf;
    const float* zwd = &g_zw[dir][0][0];

    // ---- B fragments: U fp16, permanent in registers ----
    // bfr[kt][nt][hh]: hh=0 -> k = kt*16 + lr*2 (b0 slot), hh=1 -> +8 (b1 slot)
    unsigned bfr[4][2][2];
#pragma unroll
    for (int kt = 0; kt < 4; kt++)
#pragma unroll
        for (int nt = 0; nt < 2; nt++)
#pragma unroll
            for (int hh = 0; hh < 2; hh++) {
                const int k0 = kt * 16 + lr * 2 + 8 * hh;
                const int n  = n0 + nt * 8 + lq;
                __half2 h2 = __floats2half2_rn(U[k0 * 256 + n], U[(k0 + 1) * 256 + n]);
                bfr[kt][nt][hh] = *(unsigned*)&h2;
            }

    const int cu = tid & 63;           // stage C: hidden unit
    const int cr = tid >> 6;           // stage C: row (0..7)

    // ---- prologue: token ids, zero hs16 (both buffers incl. dead rows) ----
    if (tid < 8) {
        if (tid < nrows) {
            const long long xb = (long long)(base + tid) * TSEQ;
#pragma unroll
            for (int q = 0; q < 3; q++) {
                const int tq = dir ? (TSEQ - 1 - q) : q;
                idxs[q][tid] = is64 ? (int)x64[xb + tq] : x32[xb + tq];
            }
        } else {
#pragma unroll
            for (int q = 0; q < 3; q++) idxs[q][tid] = 0;
        }
    }
    {
        unsigned* hz = (unsigned*)&hs16[0][0][0];
        const int nw = (2 * 8 * HSTR * 2) / 4;   // 576 words
        for (int i = tid; i < nw; i += 512) hz[i] = 0u;
    }
    __syncthreads();

    // zx accumulator-init values for step 0
    float2 zc0, zc1;
    {
        const long long tok = idxs[0][lq];
        zc0 = *(const float2*)(zwd + tok * 256 + n0 + lr * 2);
        zc1 = *(const float2*)(zwd + tok * 256 + n0 + 8 + lr * 2);
    }
    float hreg = 0.f, creg = 0.f;
    const unsigned zreg = 0u;

#pragma unroll 1
    for (int t = 0; t < TSEQ; t++) {
        const int p = t & 1;

        const int m = idxs[t % 3][cr];          // mask token for stage C

        // prefetch zx for step t+1
        float2 zn0, zn1;
        {
            const long long tok = idxs[(t + 1) % 3][lq];
            zn0 = *(const float2*)(zwd + tok * 256 + n0 + lr * 2);
            zn1 = *(const float2*)(zwd + tok * 256 + n0 + 8 + lr * 2);
        }
        // prefetch token id for step t+2
        if ((tid < nrows) && (t + 2 < TSEQ)) {
            const int tn = dir ? (TSEQ - 1 - (t + 2)) : (t + 2);
            const long long xb = (long long)(base + tid) * TSEQ;
            idxs[(t + 2) % 3][tid] = is64 ? (int)x64[xb + tn] : x32[xb + tn];
        }

        // ========== stage B: z = zx + h @ U  (tensor cores) ==========
        float d0[4] = {zc0.x, zc0.y, 0.f, 0.f};
        float d1[4] = {zc1.x, zc1.y, 0.f, 0.f};
#pragma unroll
        for (int kt = 0; kt < 4; kt++) {
            // aK0: rows 0-7, k = kt*16 + lr*2   -> slot a0
            // aK8: rows 0-7, k = kt*16 + lr*2+8 -> slot a2  (rows 8-15 slots = 0)
            const unsigned aK0 = *(const unsigned*)&hs16[p][lq][kt * 16 + lr * 2];
            const unsigned aK8 = *(const unsigned*)&hs16[p][lq][kt * 16 + lr * 2 + 8];
            hmma16816(d0, aK0, zreg, aK8, zreg, bfr[kt][0][0], bfr[kt][0][1]);
            hmma16816(d1, aK0, zreg, aK8, zreg, bfr[kt][1][0], bfr[kt][1][1]);
        }
        *(float2*)&zs[lq][n0 + lr * 2]     = make_float2(d0[0], d0[1]);
        *(float2*)&zs[lq][n0 + 8 + lr * 2] = make_float2(d1[0], d1[1]);
        __syncthreads();

        // ========== stage C: gates + state update ==========
        if (cr < nrows) {
            const float zi = zs[cr][cu];
            const float zf = zs[cr][64 + cu];
            const float zg = zs[cr][128 + cu];
            const float zo = zs[cr][192 + cu];
            const float ig = sigm_fast(zi);
            const float fg = sigm_fast(zf);
            const float gg = tanh_fast(zg);
            const float og = sigm_fast(zo);
            const float cn = fmaf(fg, creg, ig * gg);
            const float hn = og * tanh_fast(cn);
            if (m != 0) { creg = cn; hreg = hn; }
            hs16[p ^ 1][cr][cu] = __float2half(hreg);
        }
        zc0 = zn0; zc1 = zn1;
        __syncthreads();
    }

    if (cr < nrows)
        g_h[(dir * NB + (base + cr)) * 64 + cu] = hreg;
}

// ============================================================================
// Head: out[b] = relu(concat(hf,hb) @ W1 + b1) @ W2 + b2
// ============================================================================
extern "C" __global__ void head_kernel(const float* __restrict__ W1,
                                       const float* __restrict__ b1,
                                       const float* __restrict__ W2,
                                       const float* __restrict__ b2,
                                       float* __restrict__ out)
{
    const int b = blockIdx.x;
    const int u = threadIdx.x;
    const float* hf = &g_h[b * 64];
    const float* hb = &g_h[(NB + b) * 64];
    float acc = b1[u];
#pragma unroll
    for (int k = 0; k < 64; k++) acc = fmaf(hf[k], W1[k * 32 + u], acc);
#pragma unroll
    for (int k = 0; k < 64; k++) acc = fmaf(hb[k], W1[(64 + k) * 32 + u], acc);
    float v = fmaxf(acc, 0.f) * W2[u];
#pragma unroll
    for (int off = 16; off > 0; off >>= 1)
        v += __shfl_xor_sync(0xffffffffu, v, off);
    if (u == 0) out[b] = v + b2[0];
}

extern "C" void kernel_launch(void* const* d_in, const int* in_sizes, int n_in,
                              void* d_out, int out_size)
{
    const void*  x   = d_in[0];
    const float* emb = (const float*)d_in[1];
    const float* Wf  = (const float*)d_in[2];
    const float* Uf  = (const float*)d_in[3];
    const float* bf  = (const float*)d_in[4];
    const float* Wb  = (const float*)d_in[5];
    const float* Ub  = (const float*)d_in[6];
    const float* bb  = (const float*)d_in[7];
    const float* W1  = (const float*)d_in[8];
    const float* b1  = (const float*)d_in[9];
    const float* W2  = (const float*)d_in[10];
    const float* b2  = (const float*)d_in[11];

    zw_kernel<<<dim3((VOCABP1 + 63) / 64, 2), 256>>>(emb, Wf, bf, Wb, bb);
    lstm_kernel<<<NBLK, 512>>>(x, Uf, Ub);
    head_kernel<<<NB, 32>>>(W1, b1, W2, b2, (float*)d_out);
}

// round 9
// speedup vs baseline: 2.2111x; 1.3216x over previous
#include <cuda_runtime.h>
#include <cuda_fp16.h>

#define TSEQ    1024
#define NB      512
#define RMAX    7
#define NDIRBLK 74
#define NBLK    (2 * NDIRBLK)
#define VOCABP1 50001
#define LOG2E   1.4426950408889634f
#define HSTR    72    // hs16 row stride (halves), padded vs 64

// Precomputed zx table: zw[dir][token][gate] = emb[token] @ W_dir + b_dir
__device__ float g_zw[2][VOCABP1][256];
// final hidden states: [dir][batch][64]
__device__ float g_h[2 * NB * 64];

static __device__ __forceinline__ unsigned long long pk2(float lo, float hi) {
    unsigned long long r;
    asm("mov.b64 %0, {%1,%2};" : "=l"(r) : "f"(lo), "f"(hi));
    return r;
}
static __device__ __forceinline__ void upk2(unsigned long long v, float &lo, float &hi) {
    asm("mov.b64 {%0,%1}, %2;" : "=f"(lo), "=f"(hi) : "l"(v));
}
static __device__ __forceinline__ void ffma2(unsigned long long &d,
                                             unsigned long long a,
                                             unsigned long long b) {
    asm("fma.rn.f32x2 %0, %1, %2, %0;" : "+l"(d) : "l"(a), "l"(b));
}
static __device__ __forceinline__ float ex2a(float x) {
    float r; asm("ex2.approx.f32 %0, %1;" : "=f"(r) : "f"(x)); return r;
}
static __device__ __forceinline__ float rcpa(float x) {
    float r; asm("rcp.approx.f32 %0, %1;" : "=f"(r) : "f"(x)); return r;
}
static __device__ __forceinline__ float sigm_fast(float x) {
    return rcpa(1.f + ex2a(-LOG2E * x));
}
static __device__ __forceinline__ float tanh_fast(float x) {
    return fmaf(-2.f, rcpa(1.f + ex2a((2.f * LOG2E) * x)), 1.f);
}
static __device__ __forceinline__ void hmma16816(float* d,
                                                 unsigned a0, unsigned a1,
                                                 unsigned a2, unsigned a3,
                                                 unsigned b0, unsigned b1) {
    asm volatile(
        "mma.sync.aligned.m16n8k16.row.col.f32.f16.f16.f32 "
        "{%0,%1,%2,%3}, {%4,%5,%6,%7}, {%8,%9}, {%0,%1,%2,%3};\n"
        : "+f"(d[0]), "+f"(d[1]), "+f"(d[2]), "+f"(d[3])
        : "r"(a0), "r"(a1), "r"(a2), "r"(a3), "r"(b0), "r"(b1));
}

// ============================================================================
// Phase 1: zw[dir][v][j] = sum_k emb[v][k] * W_dir[k][j] + b_dir[j]
// ============================================================================
extern "C" __global__ void __launch_bounds__(256, 2)
zw_kernel(const float* __restrict__ emb,
          const float* __restrict__ Wf, const float* __restrict__ bf,
          const float* __restrict__ Wb, const float* __restrict__ bb)
{
    __shared__ __align__(16) float ebuf[64][64];
    const int dir  = blockIdx.y;
    const int base = blockIdx.x * 64;
    const int j    = threadIdx.x;
    const float* W  = dir ? Wb : Wf;
    const float* bv = dir ? bb : bf;

    unsigned long long wreg[32];
#pragma unroll
    for (int p = 0; p < 32; p++)
        wreg[p] = pk2(W[(2 * p) * 256 + j], W[(2 * p + 1) * 256 + j]);
    const float bj = bv[j];

#pragma unroll
    for (int i = 0; i < 16; i++) {
        const int lin = i * 256 + j;
        const int r = lin >> 6, c = lin & 63;
        const int row = base + r;
        ebuf[r][c] = (row < VOCABP1) ? emb[(long long)row * 64 + c] : 0.f;
    }
    __syncthreads();

    float* outp = &g_zw[dir][0][0];
#pragma unroll 1
    for (int r = 0; r < 64; r++) {
        if (base + r >= VOCABP1) break;
        const ulonglong2* srow = (const ulonglong2*)(&ebuf[r][0]);
        unsigned long long a0 = 0ull, a1 = 0ull;
#pragma unroll
        for (int q = 0; q < 8; q++) {
            const ulonglong2 v0 = srow[2 * q];
            const ulonglong2 v1 = srow[2 * q + 1];
            ffma2(a0, v0.x, wreg[4 * q + 0]);
            ffma2(a1, v0.y, wreg[4 * q + 1]);
            ffma2(a0, v1.x, wreg[4 * q + 2]);
            ffma2(a1, v1.y, wreg[4 * q + 3]);
        }
        float p0, p1, q0, q1;
        upk2(a0, p0, p1);
        upk2(a1, q0, q1);
        outp[(long long)(base + r) * 256 + j] = bj + ((p0 + q0) + (p1 + q1));
    }
}

// ============================================================================
// Phase 2: recurrent h@U via transposed tensor-core MMA:  z^T = U^T @ h^T.
// 148 blocks x 512 threads (16 warps), ONE barrier per step.
// Warp w owns the 16 z-columns { unit 4w+u + 64*gate : u in 0..3, gate 0..3 }
// as the MMA M-dimension; the N=8 dimension carries the sequences (fully
// used). A = U^T fp16 fragments permanent in registers (16/lane, 4 HMMA/warp
// per step). B = h^T fp16, read from smem with the same conflict-free LDS.32
// pattern validated in R8. The 4 gate pre-activations of each (row, unit)
// land inside the warp: 2 shfl.xor(16) + selects give each lane the full gate
// set for its ONE (row, unit) task -> no zs smem, no second barrier.
// hs double-buffered fp16; zx (fp32) prefetched into the accumulator inits.
// ============================================================================
extern "C" __global__ void __launch_bounds__(512, 1)
lstm_kernel(const void* __restrict__ xraw,
            const float* __restrict__ Uf, const float* __restrict__ Ub)
{
    __shared__ __align__(16) __half hs16[2][8][HSTR];  // fp16 hidden, double buf
    __shared__ int idxs[3][8];                         // token ids, 3-slot ring

    const int tid  = threadIdx.x;
    const int wid  = tid >> 5;
    const int lane = tid & 31;
    const int lq   = lane >> 2;        // 0..7
    const int lr   = lane & 3;         // 0..3
    const int g0   = lq >> 2;          // 0..1 : my "gate parity"

    const int dir   = (blockIdx.x >= NDIRBLK) ? 1 : 0;
    const int bslot = blockIdx.x - dir * NDIRBLK;
    const int base  = bslot * RMAX;
    const int nrows = min(RMAX, NB - base);

    const int uw     = wid * 4;              // unit group (4 units per warp)
    const int myunit = uw + (lq & 3);
    const int myrow  = 2 * lr + g0;          // stage C row (0..7)
    const int colA   = myunit + 64 * g0;     // z-col for c0/c1; +128 for c2/c3

    const int*       x32 = (const int*)xraw;
    const long long* x64 = (const long long*)xraw;
    const bool is64 = ((x32[1] | x32[3] | x32[5] | x32[7]) == 0);

    const float* U   = dir ? Ub : Uf;
    const float* zwd = &g_zw[dir][0][0];

    // ---- A fragments: U^T fp16, permanent in registers ----
    // afr[kt][0..3] = a0..a3 of the m16n8k16 A tile for k-chunk kt:
    //   a0: k = kt*16+2lr,+1  col = colA          a1: same k, col = colA+128
    //   a2: k = kt*16+2lr+8   col = colA          a3: same k, col = colA+128
    unsigned afr[4][4];
#pragma unroll
    for (int kt = 0; kt < 4; kt++) {
#pragma unroll
        for (int hh = 0; hh < 2; hh++) {
            const int k0 = kt * 16 + 2 * lr + 8 * hh;
            __half2 lo = __floats2half2_rn(U[k0 * 256 + colA],
                                           U[(k0 + 1) * 256 + colA]);
            __half2 hi = __floats2half2_rn(U[k0 * 256 + colA + 128],
                                           U[(k0 + 1) * 256 + colA + 128]);
            afr[kt][2 * hh]     = *(unsigned*)&lo;   // a0 (hh=0) / a2 (hh=1)
            afr[kt][2 * hh + 1] = *(unsigned*)&hi;   // a1 (hh=0) / a3 (hh=1)
        }
    }

    // ---- prologue: token ids (3-slot ring), zero both hs buffers ----
    if (tid < 8) {
        if (tid < nrows) {
            const long long xb = (long long)(base + tid) * TSEQ;
#pragma unroll
            for (int q = 0; q < 3; q++) {
                const int tq = dir ? (TSEQ - 1 - q) : q;
                idxs[q][tid] = is64 ? (int)x64[xb + tq] : x32[xb + tq];
            }
        } else {
#pragma unroll
            for (int q = 0; q < 3; q++) idxs[q][tid] = 0;
        }
    }
    {
        unsigned* hz = (unsigned*)&hs16[0][0][0];
        const int nw = (2 * 8 * HSTR * 2) / 4;
        for (int i = tid; i < nw; i += 512) hz[i] = 0u;
    }
    __syncthreads();

    // zx accumulator inits for step 0:
    //   c0: row 2lr, colA   c1: row 2lr+1, colA   c2/c3: cols +128
    float zc[4];
    {
        const long long tA = idxs[0][2 * lr];
        const long long tB = idxs[0][2 * lr + 1];
        zc[0] = zwd[tA * 256 + colA];
        zc[1] = zwd[tB * 256 + colA];
        zc[2] = zwd[tA * 256 + colA + 128];
        zc[3] = zwd[tB * 256 + colA + 128];
    }
    float hreg = 0.f, creg = 0.f;

#pragma unroll 1
    for (int t = 0; t < TSEQ; t++) {
        const int p = t & 1;

        const int m = idxs[t % 3][myrow];       // my row's mask token

        // prefetch zx for step t+1
        float zn[4];
        {
            const long long tA = idxs[(t + 1) % 3][2 * lr];
            const long long tB = idxs[(t + 1) % 3][2 * lr + 1];
            zn[0] = zwd[tA * 256 + colA];
            zn[1] = zwd[tB * 256 + colA];
            zn[2] = zwd[tA * 256 + colA + 128];
            zn[3] = zwd[tB * 256 + colA + 128];
        }
        // prefetch token id for step t+2
        if ((tid < nrows) && (t + 2 < TSEQ)) {
            const int tn = dir ? (TSEQ - 1 - (t + 2)) : (t + 2);
            const long long xb = (long long)(base + tid) * TSEQ;
            idxs[(t + 2) % 3][tid] = is64 ? (int)x64[xb + tn] : x32[xb + tn];
        }

        // ========== stage B: z^T = U^T @ h^T + zx (4 HMMA) ==========
        float d[4] = {zc[0], zc[1], zc[2], zc[3]};
#pragma unroll
        for (int kt = 0; kt < 4; kt++) {
            const unsigned b0 = *(const unsigned*)&hs16[p][lq][kt * 16 + 2 * lr];
            const unsigned b1 = *(const unsigned*)&hs16[p][lq][kt * 16 + 2 * lr + 8];
            hmma16816(d, afr[kt][0], afr[kt][1], afr[kt][2], afr[kt][3], b0, b1);
        }

        // ========== gate exchange: 2 shfl.xor(16) ==========
        // my c0/c2 (row 2lr) carry gates g0 / g0+2; c1/c3 (row 2lr+1) same.
        // Trade the off-row values so each lane has all 4 gates of myrow.
        const float sendA = g0 ? d[0] : d[1];
        const float sendB = g0 ? d[2] : d[3];
        const float recvA = __shfl_xor_sync(0xffffffffu, sendA, 16);
        const float recvB = __shfl_xor_sync(0xffffffffu, sendB, 16);
        const float zown0 = g0 ? d[1] : d[0];   // my row, gate g0
        const float zown2 = g0 ? d[3] : d[2];   // my row, gate g0+2
        const float zi = g0 ? recvA : zown0;    // gate 0
        const float zf = g0 ? zown0 : recvA;    // gate 1
        const float zg = g0 ? recvB : zown2;    // gate 2
        const float zo = g0 ? zown2 : recvB;    // gate 3

        // ========== stage C: gates + state update (1 task/thread) ==========
        {
            const float ig = sigm_fast(zi);
            const float fg = sigm_fast(zf);
            const float gg = tanh_fast(zg);
            const float og = sigm_fast(zo);
            const float cn = fmaf(fg, creg, ig * gg);
            const float hn = og * tanh_fast(cn);
            if (m != 0) { creg = cn; hreg = hn; }
            hs16[p ^ 1][myrow][myunit] = __float2half(hreg);
        }

#pragma unroll
        for (int i = 0; i < 4; i++) zc[i] = zn[i];
        __syncthreads();
    }

    if (myrow < nrows)
        g_h[(dir * NB + (base + myrow)) * 64 + myunit] = hreg;
}

// ============================================================================
// Head: out[b] = relu(concat(hf,hb) @ W1 + b1) @ W2 + b2
// ============================================================================
extern "C" __global__ void head_kernel(const float* __restrict__ W1,
                                       const float* __restrict__ b1,
                                       const float* __restrict__ W2,
                                       const float* __restrict__ b2,
                                       float* __restrict__ out)
{
    const int b = blockIdx.x;
    const int u = threadIdx.x;
    const float* hf = &g_h[b * 64];
    const float* hb = &g_h[(NB + b) * 64];
    float acc = b1[u];
#pragma unroll
    for (int k = 0; k < 64; k++) acc = fmaf(hf[k], W1[k * 32 + u], acc);
#pragma unroll
    for (int k = 0; k < 64; k++) acc = fmaf(hb[k], W1[(64 + k) * 32 + u], acc);
    float v = fmaxf(acc, 0.f) * W2[u];
#pragma unroll
    for (int off = 16; off > 0; off >>= 1)
        v += __shfl_xor_sync(0xffffffffu, v, off);
    if (u == 0) out[b] = v + b2[0];
}

extern "C" void kernel_launch(void* const* d_in, const int* in_sizes, int n_in,
                              void* d_out, int out_size)
{
    const void*  x   = d_in[0];
    const float* emb = (const float*)d_in[1];
    const float* Wf  = (const float*)d_in[2];
    const float* Uf  = (const float*)d_in[3];
    const float* bf  = (const float*)d_in[4];
    const float* Wb  = (const float*)d_in[5];
    const float* Ub  = (const float*)d_in[6];
    const float* bb  = (const float*)d_in[7];
    const float* W1  = (const float*)d_in[8];
    const float* b1  = (const float*)d_in[9];
    const float* W2  = (const float*)d_in[10];
    const float* b2  = (const float*)d_in[11];

    zw_kernel<<<dim3((VOCABP1 + 63) / 64, 2), 256>>>(emb, Wf, bf, Wb, bb);
    lstm_kernel<<<NBLK, 512>>>(x, Uf, Ub);
    head_kernel<<<NB, 32>>>(W1, b1, W2, b2, (float*)d_out);
}